// round 1
// baseline (speedup 1.0000x reference)
#include <cuda_runtime.h>
#include <cuda_bf16.h>
#include <cstdint>

// Problem constants (fixed by the dataset)
#define NN 100000
#define NE 1600000
#define HD 64
#define IND 5
#define OUTD 4
#define BN_EPS 1e-5f

// ---------------- scratch (no allocation allowed) ----------------
__device__ float  g_xw[(size_t)NN * HD];     // X @ W result
__device__ float  g_agg[(size_t)NN * HD];    // aggregated messages
__device__ float  g_dinv_s[NN];              // deg accumulator then rsqrt
__device__ float  g_dinv_t[NN];
__device__ float  g_norm_s[NE];
__device__ float  g_norm_t[NE];
__device__ double g_sum[HD];
__device__ double g_sumsq[HD];
__device__ float  g_a[HD];                   // BN scale  g*rsqrt(var+eps)
__device__ float  g_c[HD];                   // BN shift  be - mean*a

// ---------------- helpers ----------------
__device__ __forceinline__ void red_add_v4(float* addr, float4 v) {
    asm volatile("red.global.add.v4.f32 [%0], {%1,%2,%3,%4};"
                 :: "l"(addr), "f"(v.x), "f"(v.y), "f"(v.z), "f"(v.w)
                 : "memory");
}

// ---------------- kernels ----------------
__global__ void zero_f_kernel(float* p, int n) {
    int i = blockIdx.x * blockDim.x + threadIdx.x;
    if (i < n) p[i] = 0.0f;
}

__global__ void zero_stats_kernel() {
    int t = threadIdx.x;
    if (t < HD) { g_sum[t] = 0.0; g_sumsq[t] = 0.0; }
}

// deg[col] += 1 for every edge target
__global__ void deg_kernel(const int* __restrict__ cols, float* __restrict__ deg, int nE) {
    int e = blockIdx.x * blockDim.x + threadIdx.x;
    if (e < nE) atomicAdd(&deg[cols[e]], 1.0f);
}

// dinv = rsqrt(deg + 1)   (+1 = self loop)
__global__ void dinv_kernel(float* __restrict__ d, int n) {
    int i = blockIdx.x * blockDim.x + threadIdx.x;
    if (i < n) d[i] = rsqrtf(d[i] + 1.0f);
}

__global__ void norm_kernel(const int* __restrict__ rows, const int* __restrict__ cols,
                            const float* __restrict__ dinv, float* __restrict__ nrm, int nE) {
    int e = blockIdx.x * blockDim.x + threadIdx.x;
    if (e < nE) nrm[e] = dinv[rows[e]] * dinv[cols[e]];
}

// layer 1: xw = x(Nx5) @ w1(5x64)
__global__ void xw1_kernel(const float* __restrict__ x, const float* __restrict__ w,
                           float* __restrict__ out, int n) {
    __shared__ float Ws[IND][HD];
    int t = threadIdx.x;
    if (t < IND * HD) Ws[t / HD][t % HD] = w[t];
    __syncthreads();
    int idx = blockIdx.x * blockDim.x + t;
    if (idx >= n * HD) return;
    int i = idx >> 6, j = idx & 63;
    const float* xr = x + (size_t)i * IND;
    float s = 0.f;
    #pragma unroll
    for (int k = 0; k < IND; k++) s = fmaf(xr[k], Ws[k][j], s);
    out[(size_t)i * HD + j] = s;
}

// xw = relu(bn(agg)) @ W   (BN+ReLU fused into the GEMM input read)
__global__ void __launch_bounds__(128)
xw_fused_kernel(const float* __restrict__ in, const float* __restrict__ W,
                float* __restrict__ out, int n) {
    __shared__ float Ws[HD][HD];     // 16 KB
    __shared__ float as[HD], cs[HD];
    int t = threadIdx.x;
    for (int i = t; i < HD * HD; i += 128) Ws[i >> 6][i & 63] = W[i];
    if (t < HD) { as[t] = g_a[t]; cs[t] = g_c[t]; }
    __syncthreads();

    int node = blockIdx.x * 128 + t;
    if (node >= n) return;

    float acc[HD];
    #pragma unroll
    for (int j = 0; j < HD; j++) acc[j] = 0.f;

    const float* rowp = in + (size_t)node * HD;
    #pragma unroll 4
    for (int k = 0; k < HD; k++) {
        float v = fmaxf(fmaf(rowp[k], as[k], cs[k]), 0.f);
        #pragma unroll
        for (int j = 0; j < HD; j++) acc[j] = fmaf(v, Ws[k][j], acc[j]);
    }
    float4* op = (float4*)(out + (size_t)node * HD);
    #pragma unroll
    for (int q = 0; q < HD / 4; q++)
        op[q] = make_float4(acc[4*q], acc[4*q+1], acc[4*q+2], acc[4*q+3]);
}

// agg = bias + dinv^2 * xw   (self-loop term; also initializes the buffer)
__global__ void init_agg_kernel(const float* __restrict__ xw, const float* __restrict__ dinv,
                                const float* __restrict__ bias, float* __restrict__ agg, int n) {
    int idx = blockIdx.x * blockDim.x + threadIdx.x;
    if (idx >= n * (HD / 4)) return;
    int i = idx >> 4, q = idx & 15;
    float s = dinv[i]; s *= s;
    float4 v = ((const float4*)xw)[(size_t)i * 16 + q];
    float4 b = ((const float4*)bias)[q];
    ((float4*)agg)[(size_t)i * 16 + q] =
        make_float4(fmaf(s, v.x, b.x), fmaf(s, v.y, b.y),
                    fmaf(s, v.z, b.z), fmaf(s, v.w, b.w));
}

// agg[col] += norm * xw[row]   — 16 lanes per edge, vector REDs
__global__ void scatter_kernel(const int* __restrict__ rows, const int* __restrict__ cols,
                               const float* __restrict__ nrm, const float* __restrict__ xw,
                               float* __restrict__ agg, int nE) {
    int idx = blockIdx.x * blockDim.x + threadIdx.x;
    if (idx >= nE * 16) return;
    int e = idx >> 4, q = idx & 15;
    int r = rows[e], c = cols[e];
    float w = nrm[e];
    float4 v = *(const float4*)(xw + (size_t)r * HD + q * 4);
    v.x *= w; v.y *= w; v.z *= w; v.w *= w;
    red_add_v4(agg + (size_t)c * HD + q * 4, v);
}

// column sums / sumsq with double partials
__global__ void bn_stats_kernel(const float* __restrict__ agg, int n) {
    int t = threadIdx.x;              // 256
    int col = t & 63, sub = t >> 6;   // 4 sub-rows
    double s = 0.0, s2 = 0.0;
    for (int i = blockIdx.x * 4 + sub; i < n; i += gridDim.x * 4) {
        float v = agg[(size_t)i * HD + col];
        s += v; s2 += (double)v * v;
    }
    __shared__ double sh0[256], sh1[256];
    sh0[t] = s; sh1[t] = s2;
    __syncthreads();
    if (sub == 0) {
        s  = sh0[t] + sh0[t+64] + sh0[t+128] + sh0[t+192];
        s2 = sh1[t] + sh1[t+64] + sh1[t+128] + sh1[t+192];
        atomicAdd(&g_sum[col], s);
        atomicAdd(&g_sumsq[col], s2);
    }
}

__global__ void bn_finalize_kernel(const float* __restrict__ g, const float* __restrict__ be, int n) {
    int t = threadIdx.x;
    if (t >= HD) return;
    double mean = g_sum[t] / n;
    double var  = g_sumsq[t] / n - mean * mean;
    float a = g[t] * rsqrtf((float)var + BN_EPS);
    g_a[t] = a;
    g_c[t] = be[t] - (float)mean * a;
}

// out = relu(bn(agg)) @ wfc + bfc
__global__ void fc_kernel(const float* __restrict__ agg, const float* __restrict__ wfc,
                          const float* __restrict__ bfc, float* __restrict__ out, int n) {
    __shared__ float Wf[HD][OUTD];
    __shared__ float as[HD], cs[HD];
    int t = threadIdx.x;
    if (t < HD) {
        as[t] = g_a[t]; cs[t] = g_c[t];
        ((float4*)Wf)[t] = ((const float4*)wfc)[t];   // wfc row-major [64][4]
    }
    __syncthreads();
    int i = blockIdx.x * blockDim.x + t;
    if (i >= n) return;
    float a0 = bfc[0], a1 = bfc[1], a2 = bfc[2], a3 = bfc[3];
    const float* row = agg + (size_t)i * HD;
    #pragma unroll 8
    for (int k = 0; k < HD; k++) {
        float v = fmaxf(fmaf(row[k], as[k], cs[k]), 0.f);
        a0 = fmaf(v, Wf[k][0], a0);
        a1 = fmaf(v, Wf[k][1], a1);
        a2 = fmaf(v, Wf[k][2], a2);
        a3 = fmaf(v, Wf[k][3], a3);
    }
    ((float4*)out)[i] = make_float4(a0, a1, a2, a3);
}

// ---------------- host orchestration ----------------
static inline int cdiv(long long a, int b) { return (int)((a + b - 1) / b); }

extern "C" void kernel_launch(void* const* d_in, const int* in_sizes, int n_in,
                              void* d_out, int out_size) {
    const float* x   = (const float*)d_in[0];
    const int*   sei = (const int*)d_in[1];   // [2][E] int32
    const int*   tei = (const int*)d_in[2];
    const float* w1  = (const float*)d_in[3];
    const float* b1  = (const float*)d_in[4];
    const float* g1  = (const float*)d_in[5];
    const float* be1 = (const float*)d_in[6];
    const float* w2  = (const float*)d_in[7];
    const float* b2  = (const float*)d_in[8];
    const float* g2  = (const float*)d_in[9];
    const float* be2 = (const float*)d_in[10];
    const float* w3  = (const float*)d_in[11];
    const float* b3  = (const float*)d_in[12];
    const float* g3  = (const float*)d_in[13];
    const float* be3 = (const float*)d_in[14];
    const float* w4  = (const float*)d_in[15];
    const float* b4  = (const float*)d_in[16];
    const float* g4  = (const float*)d_in[17];
    const float* be4 = (const float*)d_in[18];
    const float* wfc = (const float*)d_in[19];
    const float* bfc = (const float*)d_in[20];
    float* out = (float*)d_out;

    const int n = in_sizes[0] / IND;      // 100000
    const int e = in_sizes[1] / 2;        // 1600000

    const int* s_rows = sei;      const int* s_cols = sei + e;
    const int* t_rows = tei;      const int* t_cols = tei + e;

    float* dinv_s = nullptr; cudaGetSymbolAddress((void**)&dinv_s, g_dinv_s);
    float* dinv_t = nullptr; cudaGetSymbolAddress((void**)&dinv_t, g_dinv_t);
    float* norm_s = nullptr; cudaGetSymbolAddress((void**)&norm_s, g_norm_s);
    float* norm_t = nullptr; cudaGetSymbolAddress((void**)&norm_t, g_norm_t);
    float* xw     = nullptr; cudaGetSymbolAddress((void**)&xw, g_xw);
    float* agg    = nullptr; cudaGetSymbolAddress((void**)&agg, g_agg);

    // ---- degree / norm precompute ----
    zero_f_kernel<<<cdiv(n, 256), 256>>>(dinv_s, n);
    zero_f_kernel<<<cdiv(n, 256), 256>>>(dinv_t, n);
    deg_kernel<<<cdiv(e, 256), 256>>>(s_cols, dinv_s, e);
    deg_kernel<<<cdiv(e, 256), 256>>>(t_cols, dinv_t, e);
    dinv_kernel<<<cdiv(n, 256), 256>>>(dinv_s, n);
    dinv_kernel<<<cdiv(n, 256), 256>>>(dinv_t, n);
    norm_kernel<<<cdiv(e, 256), 256>>>(s_rows, s_cols, dinv_s, norm_s, e);
    norm_kernel<<<cdiv(e, 256), 256>>>(t_rows, t_cols, dinv_t, norm_t, e);

    const int scat_grid = cdiv((long long)e * 16, 256);
    const int init_grid = cdiv((long long)n * 16, 256);

    // ---- layer 1 (spatial) ----
    xw1_kernel<<<cdiv((long long)n * HD, 320), 320>>>(x, w1, xw, n);
    init_agg_kernel<<<init_grid, 256>>>(xw, dinv_s, b1, agg, n);
    scatter_kernel<<<scat_grid, 256>>>(s_rows, s_cols, norm_s, xw, agg, e);
    zero_stats_kernel<<<1, 128>>>();
    bn_stats_kernel<<<512, 256>>>(agg, n);
    bn_finalize_kernel<<<1, 64>>>(g1, be1, n);

    // ---- layer 2 (spatial) ----
    xw_fused_kernel<<<cdiv(n, 128), 128>>>(agg, w2, xw, n);
    init_agg_kernel<<<init_grid, 256>>>(xw, dinv_s, b2, agg, n);
    scatter_kernel<<<scat_grid, 256>>>(s_rows, s_cols, norm_s, xw, agg, e);
    zero_stats_kernel<<<1, 128>>>();
    bn_stats_kernel<<<512, 256>>>(agg, n);
    bn_finalize_kernel<<<1, 64>>>(g2, be2, n);

    // ---- layer 3 (temporal) ----
    xw_fused_kernel<<<cdiv(n, 128), 128>>>(agg, w3, xw, n);
    init_agg_kernel<<<init_grid, 256>>>(xw, dinv_t, b3, agg, n);
    scatter_kernel<<<scat_grid, 256>>>(t_rows, t_cols, norm_t, xw, agg, e);
    zero_stats_kernel<<<1, 128>>>();
    bn_stats_kernel<<<512, 256>>>(agg, n);
    bn_finalize_kernel<<<1, 64>>>(g3, be3, n);

    // ---- layer 4 (temporal) ----
    xw_fused_kernel<<<cdiv(n, 128), 128>>>(agg, w4, xw, n);
    init_agg_kernel<<<init_grid, 256>>>(xw, dinv_t, b4, agg, n);
    scatter_kernel<<<scat_grid, 256>>>(t_rows, t_cols, norm_t, xw, agg, e);
    zero_stats_kernel<<<1, 128>>>();
    bn_stats_kernel<<<512, 256>>>(agg, n);
    bn_finalize_kernel<<<1, 64>>>(g4, be4, n);

    // ---- final FC ----
    fc_kernel<<<cdiv(n, 256), 256>>>(agg, wfc, bfc, out, n);
}

// round 3
// speedup vs baseline: 1.1309x; 1.1309x over previous
#include <cuda_runtime.h>
#include <cstdint>

#define NN 100000
#define NE 1600000
#define HD 64
#define IND 5
#define OUTD 4
#define BN_EPS 1e-5f
#define TS 65   // padded tile row stride (floats)

// ---------------- scratch (static; no allocation allowed) ----------------
__device__ float  g_xw[(size_t)NN * HD];
__device__ float  g_agg[(size_t)NN * HD];
__device__ int    g_cnt_s[NN], g_cnt_t[NN];      // edge-target counts (int)
__device__ int    g_start_s[NN], g_start_t[NN];  // CSR offsets (exclusive scan)
__device__ int    g_cur_s[NN],  g_cur_t[NN];     // placement cursors
__device__ float  g_dv_s[NN],  g_dv_t[NN];       // rsqrt(deg+1)
__device__ int2   g_adj_s[NE], g_adj_t[NE];      // (row, norm-bits) per edge, grouped by col
__device__ double g_sum[HD], g_sumsq[HD];
__device__ float  g_a[HD], g_c[HD];              // BN scale/shift

static inline int cdiv(long long a, int b) { return (int)((a + b - 1) / b); }

// ---------------- CSR build ----------------
__global__ void zero_cnt_kernel(int* a, int* b, int n) {
    int i = blockIdx.x * blockDim.x + threadIdx.x;
    if (i < n) { a[i] = 0; b[i] = 0; }
}

__global__ void count_kernel(const int* __restrict__ cols, int* __restrict__ cnt, int nE) {
    int e = blockIdx.x * blockDim.x + threadIdx.x;
    if (e < nE) atomicAdd(&cnt[cols[e]], 1);
}

__global__ void dinv_kernel(const int* __restrict__ ca, const int* __restrict__ cb,
                            float* __restrict__ da, float* __restrict__ db, int n) {
    int i = blockIdx.x * blockDim.x + threadIdx.x;
    if (i < n) {
        da[i] = rsqrtf((float)ca[i] + 1.0f);
        db[i] = rsqrtf((float)cb[i] + 1.0f);
    }
}

// grid = 2 blocks (one per graph), 1024 threads. Exclusive scan of counts.
__global__ void scan_kernel(const int* __restrict__ cnt_s, int* __restrict__ start_s, int* __restrict__ cur_s,
                            const int* __restrict__ cnt_t, int* __restrict__ start_t, int* __restrict__ cur_t,
                            int n) {
    const int* cnt = blockIdx.x ? cnt_t : cnt_s;
    int* start = blockIdx.x ? start_t : start_s;
    int* cur   = blockIdx.x ? cur_t   : cur_s;
    int t = threadIdx.x;
    int chunk = (n + 1023) / 1024;
    int lo = t * chunk, hi = min(lo + chunk, n);
    int s = 0;
    for (int i = lo; i < hi; i++) s += cnt[i];
    __shared__ int sh[1024];
    sh[t] = s;
    __syncthreads();
    for (int off = 1; off < 1024; off <<= 1) {
        int v = (t >= off) ? sh[t - off] : 0;
        __syncthreads();
        sh[t] += v;
        __syncthreads();
    }
    int run = (t == 0) ? 0 : sh[t - 1];
    for (int i = lo; i < hi; i++) {
        start[i] = run; cur[i] = run;
        run += cnt[i];
    }
}

__global__ void place_kernel(const int* __restrict__ rows, const int* __restrict__ cols,
                             const float* __restrict__ dinv, int* __restrict__ cur,
                             int2* __restrict__ adj, int nE) {
    int e = blockIdx.x * blockDim.x + threadIdx.x;
    if (e >= nE) return;
    int r = rows[e], c = cols[e];
    int pos = atomicAdd(&cur[c], 1);
    float w = dinv[r] * dinv[c];
    adj[pos] = make_int2(r, __float_as_int(w));
}

// ---------------- layer 1 projection: xw = x(Nx5) @ w1(5x64) ----------------
__global__ void xw1_kernel(const float* __restrict__ x, const float* __restrict__ w,
                           float* __restrict__ out, int n) {
    __shared__ float Ws[IND * HD];
    int t = threadIdx.x;
    for (int i = t; i < IND * HD; i += blockDim.x) Ws[i] = w[i];   // FIXED: strided load
    __syncthreads();
    int idx = blockIdx.x * blockDim.x + t;
    int node = idx >> 4, q = idx & 15;
    if (node >= n) return;
    float xr[IND];
    #pragma unroll
    for (int k = 0; k < IND; k++) xr[k] = __ldg(&x[(size_t)node * IND + k]);
    float4 a = make_float4(0.f, 0.f, 0.f, 0.f);
    #pragma unroll
    for (int k = 0; k < IND; k++) {
        const float* wr = &Ws[k * HD + q * 4];
        a.x = fmaf(xr[k], wr[0], a.x);
        a.y = fmaf(xr[k], wr[1], a.y);
        a.z = fmaf(xr[k], wr[2], a.z);
        a.w = fmaf(xr[k], wr[3], a.w);
    }
    ((float4*)out)[(size_t)node * 16 + q] = a;
}

// ---------------- atomic-free aggregation (gather over CSR) ----------------
// agg[c] = b + dinv[c]^2 * xw[c] + sum_{edges into c} norm * xw[row]
// 16 lanes per node; also zeroes BN stats (block 0) for the following bn_stats.
__global__ void __launch_bounds__(256)
gather_kernel(const int2* __restrict__ adj, const int* __restrict__ start,
              const int* __restrict__ cnt, const float* __restrict__ dinv,
              const float* __restrict__ xw, const float* __restrict__ bias,
              float* __restrict__ agg, int n) {
    int t = threadIdx.x;
    if (blockIdx.x == 0 && t < HD) { g_sum[t] = 0.0; g_sumsq[t] = 0.0; }
    int idx = blockIdx.x * 256 + t;
    int node = idx >> 4, q = idx & 15;
    if (node >= n) return;
    const float4* xw4 = (const float4*)xw;

    float4 acc = __ldg(&((const float4*)bias)[q]);
    float s = dinv[node]; s *= s;
    float4 self = __ldg(&xw4[(size_t)node * 16 + q]);
    acc.x = fmaf(s, self.x, acc.x);
    acc.y = fmaf(s, self.y, acc.y);
    acc.z = fmaf(s, self.z, acc.z);
    acc.w = fmaf(s, self.w, acc.w);

    int p0 = start[node];
    int p1 = p0 + cnt[node];
    #pragma unroll 2
    for (int p = p0; p < p1; p++) {
        int2 a = __ldg(&adj[p]);
        float w = __int_as_float(a.y);
        float4 v = __ldg(&xw4[(size_t)a.x * 16 + q]);
        acc.x = fmaf(w, v.x, acc.x);
        acc.y = fmaf(w, v.y, acc.y);
        acc.z = fmaf(w, v.z, acc.z);
        acc.w = fmaf(w, v.w, acc.w);
    }
    ((float4*)agg)[(size_t)node * 16 + q] = acc;
}

// ---------------- BN stats: column sums / sumsq ----------------
__global__ void bn_stats_kernel(const float* __restrict__ agg, int n) {
    int t = threadIdx.x;              // 256
    int col = t & 63, sub = t >> 6;   // 4 sub-rows
    float s = 0.f, s2 = 0.f;
    for (int i = blockIdx.x * 4 + sub; i < n; i += gridDim.x * 4) {
        float v = agg[(size_t)i * HD + col];
        s += v;
        s2 = fmaf(v, v, s2);
    }
    __shared__ float sh0[256], sh1[256];
    sh0[t] = s; sh1[t] = s2;
    __syncthreads();
    if (sub == 0) {
        double ds  = (double)sh0[t] + sh0[t + 64] + sh0[t + 128] + sh0[t + 192];
        double ds2 = (double)sh1[t] + sh1[t + 64] + sh1[t + 128] + sh1[t + 192];
        atomicAdd(&g_sum[col], ds);
        atomicAdd(&g_sumsq[col], ds2);
    }
}

__global__ void bn_finalize_kernel(const float* __restrict__ g, const float* __restrict__ be, int n) {
    int t = threadIdx.x;
    if (t >= HD) return;
    double mean = g_sum[t] / n;
    double var  = g_sumsq[t] / n - mean * mean;
    float a = g[t] * rsqrtf((float)var + BN_EPS);
    g_a[t] = a;
    g_c[t] = be[t] - (float)mean * a;
}

// ---------------- fused BN+ReLU+GEMM: xw = relu(bn(agg)) @ W ----------------
// block = 128 threads = 64 nodes, 2 threads per node (32 outputs each).
__global__ void __launch_bounds__(128)
xw_fused_kernel(const float* __restrict__ in, const float* __restrict__ W,
                float* __restrict__ out, int n) {
    __shared__ float tile[64 * TS];
    __shared__ float Ws[HD * HD];
    __shared__ float as[HD], cs[HD];
    int t = threadIdx.x;
    for (int i = t; i < HD * HD; i += 128) Ws[i] = W[i];
    if (t < HD) { as[t] = g_a[t]; cs[t] = g_c[t]; }

    int base = blockIdx.x * 64;
    int nv = min(64, n - base);
    const float4* in4 = (const float4*)(in + (size_t)base * HD);
    for (int i = t; i < nv * 16; i += 128) {
        float4 v = __ldg(&in4[i]);
        float* p = &tile[(i >> 4) * TS + (i & 15) * 4];
        p[0] = v.x; p[1] = v.y; p[2] = v.z; p[3] = v.w;
    }
    __syncthreads();

    int node = t >> 1, h = t & 1;
    bool act = (base + node) < n;
    float acc[32];
    #pragma unroll
    for (int j = 0; j < 32; j++) acc[j] = 0.f;
    if (act) {
        const float* row = &tile[node * TS];
        const float* wb  = &Ws[h * 32];
        #pragma unroll 4
        for (int k = 0; k < HD; k++) {
            float v = fmaxf(fmaf(row[k], as[k], cs[k]), 0.f);
            #pragma unroll
            for (int j = 0; j < 32; j++) acc[j] = fmaf(v, wb[k * HD + j], acc[j]);
        }
    }
    __syncthreads();
    if (act) {
        float* dst = &tile[node * TS + h * 32];
        #pragma unroll
        for (int j = 0; j < 32; j++) dst[j] = acc[j];
    }
    __syncthreads();
    float4* out4 = (float4*)(out + (size_t)base * HD);
    for (int i = t; i < nv * 16; i += 128) {
        float* p = &tile[(i >> 4) * TS + (i & 15) * 4];
        out4[i] = make_float4(p[0], p[1], p[2], p[3]);
    }
}

// ---------------- final FC: out = relu(bn(agg)) @ wfc + bfc ----------------
__global__ void __launch_bounds__(128)
fc_kernel(const float* __restrict__ agg, const float* __restrict__ wfc,
          const float* __restrict__ bfc, float* __restrict__ out, int n) {
    __shared__ float tile[128 * TS];
    __shared__ float Wf[HD * OUTD];
    __shared__ float as[HD], cs[HD];
    int t = threadIdx.x;
    if (t < HD) { as[t] = g_a[t]; cs[t] = g_c[t]; }
    if (t < HD) ((float4*)Wf)[t] = ((const float4*)wfc)[t];

    int base = blockIdx.x * 128;
    int nv = min(128, n - base);
    const float4* in4 = (const float4*)(agg + (size_t)base * HD);
    for (int i = t; i < nv * 16; i += 128) {
        float4 v = __ldg(&in4[i]);
        float* p = &tile[(i >> 4) * TS + (i & 15) * 4];
        p[0] = v.x; p[1] = v.y; p[2] = v.z; p[3] = v.w;
    }
    __syncthreads();
    if (t < nv) {
        float a0 = __ldg(&bfc[0]), a1 = __ldg(&bfc[1]);
        float a2 = __ldg(&bfc[2]), a3 = __ldg(&bfc[3]);
        const float* row = &tile[t * TS];
        #pragma unroll 8
        for (int k = 0; k < HD; k++) {
            float v = fmaxf(fmaf(row[k], as[k], cs[k]), 0.f);
            a0 = fmaf(v, Wf[k * 4 + 0], a0);
            a1 = fmaf(v, Wf[k * 4 + 1], a1);
            a2 = fmaf(v, Wf[k * 4 + 2], a2);
            a3 = fmaf(v, Wf[k * 4 + 3], a3);
        }
        ((float4*)out)[base + t] = make_float4(a0, a1, a2, a3);
    }
}

// ---------------- host orchestration ----------------
extern "C" void kernel_launch(void* const* d_in, const int* in_sizes, int n_in,
                              void* d_out, int out_size) {
    const float* x   = (const float*)d_in[0];
    const int*   sei = (const int*)d_in[1];
    const int*   tei = (const int*)d_in[2];
    const float* w1  = (const float*)d_in[3];
    const float* b1  = (const float*)d_in[4];
    const float* g1  = (const float*)d_in[5];
    const float* be1 = (const float*)d_in[6];
    const float* w2  = (const float*)d_in[7];
    const float* b2  = (const float*)d_in[8];
    const float* g2  = (const float*)d_in[9];
    const float* be2 = (const float*)d_in[10];
    const float* w3  = (const float*)d_in[11];
    const float* b3  = (const float*)d_in[12];
    const float* g3  = (const float*)d_in[13];
    const float* be3 = (const float*)d_in[14];
    const float* w4  = (const float*)d_in[15];
    const float* b4  = (const float*)d_in[16];
    const float* g4  = (const float*)d_in[17];
    const float* be4 = (const float*)d_in[18];
    const float* wfc = (const float*)d_in[19];
    const float* bfc = (const float*)d_in[20];
    float* out = (float*)d_out;

    const int n = in_sizes[0] / IND;   // 100000
    const int e = in_sizes[1] / 2;     // 1600000
    const int* s_rows = sei;  const int* s_cols = sei + e;
    const int* t_rows = tei;  const int* t_cols = tei + e;

    int *cnt_s, *cnt_t, *start_s, *start_t, *cur_s, *cur_t;
    float *dv_s, *dv_t, *xw, *agg;
    int2 *adj_s, *adj_t;
    cudaGetSymbolAddress((void**)&cnt_s, g_cnt_s);
    cudaGetSymbolAddress((void**)&cnt_t, g_cnt_t);
    cudaGetSymbolAddress((void**)&start_s, g_start_s);
    cudaGetSymbolAddress((void**)&start_t, g_start_t);
    cudaGetSymbolAddress((void**)&cur_s, g_cur_s);
    cudaGetSymbolAddress((void**)&cur_t, g_cur_t);
    cudaGetSymbolAddress((void**)&dv_s, g_dv_s);
    cudaGetSymbolAddress((void**)&dv_t, g_dv_t);
    cudaGetSymbolAddress((void**)&xw, g_xw);
    cudaGetSymbolAddress((void**)&agg, g_agg);
    cudaGetSymbolAddress((void**)&adj_s, g_adj_s);
    cudaGetSymbolAddress((void**)&adj_t, g_adj_t);

    const int eg = cdiv(e, 256);
    const int ng16 = cdiv((long long)n * 16, 256);

    // ---- CSR build (once per graph, reused by 2 layers each) ----
    zero_cnt_kernel<<<cdiv(n, 256), 256>>>(cnt_s, cnt_t, n);
    count_kernel<<<eg, 256>>>(s_cols, cnt_s, e);
    count_kernel<<<eg, 256>>>(t_cols, cnt_t, e);
    dinv_kernel<<<cdiv(n, 256), 256>>>(cnt_s, cnt_t, dv_s, dv_t, n);
    scan_kernel<<<2, 1024>>>(cnt_s, start_s, cur_s, cnt_t, start_t, cur_t, n);
    place_kernel<<<eg, 256>>>(s_rows, s_cols, dv_s, cur_s, adj_s, e);
    place_kernel<<<eg, 256>>>(t_rows, t_cols, dv_t, cur_t, adj_t, e);

    // ---- layer 1 (spatial) ----
    xw1_kernel<<<ng16, 256>>>(x, w1, xw, n);
    gather_kernel<<<ng16, 256>>>(adj_s, start_s, cnt_s, dv_s, xw, b1, agg, n);
    bn_stats_kernel<<<512, 256>>>(agg, n);
    bn_finalize_kernel<<<1, 64>>>(g1, be1, n);

    // ---- layer 2 (spatial) ----
    xw_fused_kernel<<<cdiv(n, 64), 128>>>(agg, w2, xw, n);
    gather_kernel<<<ng16, 256>>>(adj_s, start_s, cnt_s, dv_s, xw, b2, agg, n);
    bn_stats_kernel<<<512, 256>>>(agg, n);
    bn_finalize_kernel<<<1, 64>>>(g2, be2, n);

    // ---- layer 3 (temporal) ----
    xw_fused_kernel<<<cdiv(n, 64), 128>>>(agg, w3, xw, n);
    gather_kernel<<<ng16, 256>>>(adj_t, start_t, cnt_t, dv_t, xw, b3, agg, n);
    bn_stats_kernel<<<512, 256>>>(agg, n);
    bn_finalize_kernel<<<1, 64>>>(g3, be3, n);

    // ---- layer 4 (temporal) ----
    xw_fused_kernel<<<cdiv(n, 64), 128>>>(agg, w4, xw, n);
    gather_kernel<<<ng16, 256>>>(adj_t, start_t, cnt_t, dv_t, xw, b4, agg, n);
    bn_stats_kernel<<<512, 256>>>(agg, n);
    bn_finalize_kernel<<<1, 64>>>(g4, be4, n);

    // ---- final FC ----
    fc_kernel<<<cdiv(n, 128), 128>>>(agg, wfc, bfc, out, n);
}